// round 14
// baseline (speedup 1.0000x reference)
#include <cuda_runtime.h>
#include <cuda.h>
#include <cuda_fp16.h>
#include <cstdint>
#include <math.h>
#include <dlfcn.h>

#define SEQ   2048
#define BATCH 32
#define HDIM  1024
#define MROWS (SEQ * BATCH)

#define BM    128
#define BN    128
#define NPASS 8
#define BK    64
#define KT    16
#define DEPTH 2
#define CLUSTER 4

#define A_STAGE_BYTES (BM * 128)
#define B_STAGE_BYTES (BN * 128)
#define B_SLICE_BYTES (B_STAGE_BYTES / CLUSTER)
#define STAGE_BYTES   (A_STAGE_BYTES + B_STAGE_BYTES)
#define TX_BYTES      STAGE_BYTES

#define CS_OFF   (DEPTH * STAGE_BYTES)            // 65536
#define SRED_OFF (CS_OFF + 32 * 129 * 4)          // 82048
#define BAR_OFF  (SRED_OFF + 4 * 128 * 4)         // 84096
#define SMEM_TOTAL (BAR_OFF + 32 + 1024)

__device__ __align__(1024) __half g_enc_h[(size_t)MROWS * HDIM];  // 128 MB
__device__ __align__(1024) __half g_wb_h[(size_t)HDIM * HDIM];    // 2 MB
__device__ float g_c[BATCH * HDIM];
__device__ float g_scores[BATCH * SEQ];

// ---------------------------------------------------------------------------
__device__ __forceinline__ uint32_t smem_u32(const void* p) {
    uint32_t a;
    asm("{ .reg .u64 t; cvta.to.shared.u64 t, %1; cvt.u32.u64 %0, t; }" : "=r"(a) : "l"(p));
    return a;
}
__device__ __forceinline__ uint32_t elect_one() {
    uint32_t p;
    asm volatile("{ .reg .pred p; elect.sync _|p, 0xFFFFFFFF; selp.b32 %0, 1, 0, p; }" : "=r"(p));
    return p;
}
__device__ __forceinline__ uint32_t ctarank() {
    uint32_t r; asm("mov.u32 %0, %%cluster_ctarank;" : "=r"(r)); return r;
}
__device__ __forceinline__ uint32_t mapa_addr(uint32_t a, uint32_t r) {
    uint32_t ra;
    asm("mapa.shared::cluster.u32 %0, %1, %2;" : "=r"(ra) : "r"(a), "r"(r));
    return ra;
}

#define MBAR_INIT(a, n) \
    asm volatile("mbarrier.init.shared.b64 [%0], %1;" :: "r"(a), "r"((uint32_t)(n)) : "memory")
#define MBAR_EXPECT_TX(a, n) \
    asm volatile("mbarrier.arrive.expect_tx.shared.b64 _, [%0], %1;" :: "r"(a), "r"((uint32_t)(n)) : "memory")
#define MBAR_ARRIVE_REMOTE(ra) \
    asm volatile("mbarrier.arrive.shared::cluster.b64 _, [%0];" :: "r"(ra) : "memory")
#define MBAR_WAIT(a, ph) do { \
    uint32_t _m = (a), _p = (ph), _d; \
    asm volatile("{ .reg .pred p; mbarrier.try_wait.parity.acquire.cta.shared::cta.b64 p, [%1], %2; selp.b32 %0,1,0,p; }" \
        : "=r"(_d) : "r"(_m), "r"(_p) : "memory"); \
    if (!_d) { \
        asm volatile("{ .reg .pred P1;\nWL_%=:\n mbarrier.try_wait.parity.acquire.cta.shared::cta.b64 P1, [%0], %1, 0x989680;\n @P1 bra.uni WD_%=;\n bra.uni WL_%=;\nWD_%=:\n}" \
            :: "r"(_m), "r"(_p) : "memory"); \
    } } while (0)

#define TMA2D_CTA(smem, map, x, y, bar) \
    asm volatile("cp.async.bulk.tensor.2d.shared::cta.global.tile.mbarrier::complete_tx::bytes [%0], [%1, {%2, %3}], [%4];" \
        :: "r"(smem), "l"(map), "r"((int)(x)), "r"((int)(y)), "r"(bar) : "memory")
#define TMA2D_MCAST(smem, map, x, y, bar, mask) \
    asm volatile("cp.async.bulk.tensor.2d.shared::cluster.global.tile.mbarrier::complete_tx::bytes.multicast::cluster [%0], [%1, {%2, %3}], [%4], %5;" \
        :: "r"(smem), "l"(map), "r"((int)(x)), "r"((int)(y)), "r"(bar), "h"((uint16_t)(mask)) : "memory")

#define LDSM4(r, a) \
    asm volatile("ldmatrix.sync.aligned.m8n8.x4.shared.b16 {%0,%1,%2,%3}, [%4];" \
        : "=r"((r)[0]), "=r"((r)[1]), "=r"((r)[2]), "=r"((r)[3]) : "r"(a))

__device__ __forceinline__ void mma_f16(float* c, const uint32_t* a, uint32_t b0, uint32_t b1) {
    asm volatile(
        "mma.sync.aligned.m16n8k16.row.col.f32.f16.f16.f32 "
        "{%0,%1,%2,%3}, {%4,%5,%6,%7}, {%8,%9}, {%0,%1,%2,%3};"
        : "+f"(c[0]), "+f"(c[1]), "+f"(c[2]), "+f"(c[3])
        : "r"(a[0]), "r"(a[1]), "r"(a[2]), "r"(a[3]), "r"(b0), "r"(b1));
}

__device__ __forceinline__ float fast_tanh(float x) {
    float e, r;
    asm("ex2.approx.f32 %0, %1;" : "=f"(e) : "f"(x * 2.8853900817779268f));
    asm("rcp.approx.f32 %0, %1;" : "=f"(r) : "f"(e + 1.0f));
    return fmaf(-2.0f, r, 1.0f);
}
__device__ __forceinline__ uint32_t pack2h(float a, float b) {
    __half2 h = __floats2half2_rn(a, b);
    return *(uint32_t*)&h;
}
__device__ __forceinline__ float4 ldcs4(const float4* p) {
    float4 r;
    asm("ld.global.cs.v4.f32 {%0,%1,%2,%3}, [%4];"
        : "=f"(r.x), "=f"(r.y), "=f"(r.z), "=f"(r.w) : "l"(p));
    return r;
}

// ---------------------------------------------------------------------------
// Small prep: blocks [0, NB_W) convert W (We -> f16); [NB_W, +1024) compute c.
// enc conversion moved into the GEMM CTAs (each converts its own slice).
// ---------------------------------------------------------------------------
#define NB_W   (HDIM * HDIM / 8 / 256)    // 512

__global__ __launch_bounds__(256)
void prep_small_kernel(const float* __restrict__ W,
                       const float* __restrict__ hidden,
                       const float* __restrict__ bias) {
    const int bx = blockIdx.x;
    if (bx < NB_W) {
        size_t i = (size_t)bx * 256 + threadIdx.x;
        int n = (int)(i >> 7), k8 = ((int)i & 127) * 8;
        const float4* src = (const float4*)(W + (size_t)n * (2 * HDIM) + HDIM + k8);
        float4 f0 = src[0], f1 = src[1];
        uint4 o;
        o.x = pack2h(f0.x, f0.y); o.y = pack2h(f0.z, f0.w);
        o.z = pack2h(f1.x, f1.y); o.w = pack2h(f1.z, f1.w);
        ((uint4*)g_wb_h)[i] = o;
        return;
    }
    // prep_c: one block per k
    __shared__ float sw[HDIM];
    const int k = bx - NB_W;
    const int tid = threadIdx.x;
    for (int j = tid; j < HDIM; j += 256) sw[j] = W[(size_t)k * (2 * HDIM) + j];
    __syncthreads();
    const int w = tid >> 5, l = tid & 31;
    const float bk = bias[k];
    for (int b = w; b < 32; b += 8) {
        const float* h = hidden + (size_t)b * HDIM;
        float acc = 0.f;
        #pragma unroll 8
        for (int j = l; j < HDIM; j += 32) acc += h[j] * sw[j];
        acc += __shfl_xor_sync(~0u, acc, 16);
        acc += __shfl_xor_sync(~0u, acc, 8);
        acc += __shfl_xor_sync(~0u, acc, 4);
        acc += __shfl_xor_sync(~0u, acc, 2);
        acc += __shfl_xor_sync(~0u, acc, 1);
        if (l == 0) g_c[b * HDIM + k] = acc + bk;
    }
}

// ---------------------------------------------------------------------------
// Fused GEMM (r10 config) + in-kernel A-slice conversion.
// ---------------------------------------------------------------------------
__global__ __launch_bounds__(288, 2) __cluster_dims__(CLUSTER, 1, 1)
void gemm_fused_kernel(const float4* __restrict__ enc4,
                       const __grid_constant__ CUtensorMap tmap_a,
                       const __grid_constant__ CUtensorMap tmap_b,
                       const float* __restrict__ v) {
    extern __shared__ char smem_raw[];
    const uint32_t sraw = smem_u32(smem_raw);
    const uint32_t base = (sraw + 1023u) & ~1023u;
    char* sm = smem_raw + (base - sraw);

    const int tid  = threadIdx.x;
    const int wid  = tid >> 5;
    const int lane = tid & 31;
    const uint32_t rank = ctarank();
    const int m0 = blockIdx.x * BM;

    float* cs   = (float*)(sm + CS_OFF);    // [32][129]
    float* sred = (float*)(sm + SRED_OFF);  // [4][128]

    // ---- convert this CTA's A slice: rows [m0, m0+BM), all HDIM cols ----
    {
        // slice = BM*HDIM floats = 16384 vec8 chunks; 288 threads
        const size_t base8 = (size_t)m0 * (HDIM / 8);   // vec8 index of slice start
        for (int i = tid; i < BM * HDIM / 8; i += 288) {
            const size_t gi = base8 + (size_t)i;
            float4 f0 = ldcs4(&enc4[2 * gi]);
            float4 f1 = ldcs4(&enc4[2 * gi + 1]);
            uint4 o;
            o.x = pack2h(f0.x, f0.y); o.y = pack2h(f0.z, f0.w);
            o.z = pack2h(f1.x, f1.y); o.w = pack2h(f1.z, f1.w);
            ((uint4*)g_enc_h)[gi] = o;
        }
        __threadfence();
        __syncthreads();
        asm volatile("fence.proxy.async;" ::: "memory");
    }

    const uint32_t full0  = base + BAR_OFF;        // DEPTH x 8
    const uint32_t empty0 = base + BAR_OFF + 16;   // DEPTH x 8

    if (tid == 0) {
        #pragma unroll
        for (int s = 0; s < DEPTH; s++) {
            MBAR_INIT(full0  + s * 8, 1);
            MBAR_INIT(empty0 + s * 8, 8 * CLUSTER);
        }
    }
    __syncthreads();
    asm volatile("barrier.cluster.arrive.aligned;" ::: "memory");
    asm volatile("barrier.cluster.wait.aligned;"   ::: "memory");

    if (wid == 8) {
        // -------- TMA producer --------
        if (elect_one()) {
            int stage = 0, ph = 1;
            for (int i = 0; i < NPASS * KT; i++) {
                const int p = i >> 4, kt = i & 15;
                MBAR_WAIT(empty0 + stage * 8, ph);
                const uint32_t fb = full0 + stage * 8;
                MBAR_EXPECT_TX(fb, TX_BYTES);
                const uint32_t a_dst = base + stage * STAGE_BYTES;
                const uint32_t b_dst = a_dst + A_STAGE_BYTES + rank * B_SLICE_BYTES;
                TMA2D_CTA(a_dst, &tmap_a, kt * BK, m0, fb);
                TMA2D_MCAST(b_dst, &tmap_b, kt * BK, p * BN + (int)rank * 32, fb, 0xF);
                if (++stage == DEPTH) { stage = 0; ph ^= 1; }
            }
        }
    } else {
        // -------- consumers: warps 0-7, warp tile 64x32 --------
        const int warp_m = wid >> 2;
        const int warp_n = wid & 3;

        uint32_t remote_empty[DEPTH];
        if (lane < CLUSTER) {
            #pragma unroll
            for (int s = 0; s < DEPTH; s++)
                remote_empty[s] = mapa_addr(empty0 + s * 8, (uint32_t)lane);
        }

        float acc[4][4][4];
        float score[8];
        #pragma unroll
        for (int i = 0; i < 8; i++) score[i] = 0.f;
        #pragma unroll
        for (int mt = 0; mt < 4; mt++)
            #pragma unroll
            for (int nt = 0; nt < 4; nt++)
                #pragma unroll
                for (int i = 0; i < 4; i++) acc[mt][nt][i] = 0.f;

        const int g   = lane >> 2;
        const int tig = lane & 3;
        const int a_row = warp_m * 64 + (lane & 15);
        const uint32_t a_ghi = (uint32_t)(lane >> 4);
        const int b_row = warp_n * 32 + ((lane >> 3) & 1) * 8 + (lane & 7);

        int stage = 0, fph = 0;
        for (int p = 0; p < NPASS; p++) {
            asm volatile("bar.sync 1, 256;" ::: "memory");
            for (int idx = tid; idx < 32 * BN; idx += 256) {
                const int b = idx >> 7, nn = idx & 127;
                cs[b * 129 + nn] = g_c[b * HDIM + p * BN + nn];
            }
            asm volatile("bar.sync 1, 256;" ::: "memory");

            for (int kt = 0; kt < KT; kt++) {
                MBAR_WAIT(full0 + stage * 8, fph);
                const uint32_t a_base = base + stage * STAGE_BYTES;
                const uint32_t b_base = a_base + A_STAGE_BYTES;
                #pragma unroll
                for (int ks = 0; ks < 4; ks++) {
                    const uint32_t gr = (uint32_t)(ks * 2) + a_ghi;
                    uint32_t aF[4][4], bF[2][4];
                    #pragma unroll
                    for (int mt = 0; mt < 4; mt++) {
                        const int r = a_row + mt * 16;
                        LDSM4(aF[mt], a_base + r * 128 + ((gr ^ (uint32_t)(r & 7)) << 4));
                    }
                    #pragma unroll
                    for (int ntp = 0; ntp < 2; ntp++) {
                        const int n = b_row + ntp * 16;
                        LDSM4(bF[ntp], b_base + n * 128 + ((gr ^ (uint32_t)(n & 7)) << 4));
                    }
                    #pragma unroll
                    for (int mt = 0; mt < 4; mt++)
                        #pragma unroll
                        for (int ntp = 0; ntp < 2; ntp++) {
                            mma_f16(acc[mt][2 * ntp],     aF[mt], bF[ntp][0], bF[ntp][2]);
                            mma_f16(acc[mt][2 * ntp + 1], aF[mt], bF[ntp][1], bF[ntp][3]);
                        }
                }
                if (lane < CLUSTER) MBAR_ARRIVE_REMOTE(remote_empty[stage]);
                if (++stage == DEPTH) { stage = 0; fph ^= 1; }
            }

            // epilogue: tanh + v-dot
            #pragma unroll
            for (int mt = 0; mt < 4; mt++) {
                #pragma unroll
                for (int nt = 0; nt < 4; nt++) {
                    #pragma unroll
                    for (int i = 0; i < 4; i++) {
                        const int rl  = mt * 16 + g + ((i >> 1) << 3);
                        const int b   = rl & 31;
                        const int col = warp_n * 32 + nt * 8 + (tig << 1) + (i & 1);
                        const float vv = __ldg(&v[p * BN + col]);
                        score[mt * 2 + (i >> 1)] +=
                            fast_tanh(acc[mt][nt][i] + cs[b * 129 + col]) * vv;
                        acc[mt][nt][i] = 0.f;
                    }
                }
            }
        }

        #pragma unroll
        for (int slot = 0; slot < 8; slot++) {
            float sv = score[slot];
            sv += __shfl_xor_sync(0xFFFFFFFFu, sv, 1);
            sv += __shfl_xor_sync(0xFFFFFFFFu, sv, 2);
            if (tig == 0) {
                const int rl = warp_m * 64 + (slot >> 1) * 16 + g + ((slot & 1) << 3);
                sred[warp_n * 128 + rl] = sv;
            }
        }
        asm volatile("bar.sync 1, 256;" ::: "memory");
        if (tid < BM) {
            const float t = sred[tid] + sred[128 + tid] + sred[256 + tid] + sred[384 + tid];
            const int m = m0 + tid;
            g_scores[(m & 31) * SEQ + (m >> 5)] = t;
        }
    }

    __syncthreads();
    asm volatile("barrier.cluster.arrive.aligned;" ::: "memory");
    asm volatile("barrier.cluster.wait.aligned;"   ::: "memory");
}

// ---------------------------------------------------------------------------
__global__ void softmax_kernel(float* __restrict__ out) {
    __shared__ float red[256];
    const int b = blockIdx.x, tid = threadIdx.x;
    const float* sc = g_scores + b * SEQ;

    float m = -1e30f;
    for (int s = tid; s < SEQ; s += 256) m = fmaxf(m, sc[s]);
    red[tid] = m;
    __syncthreads();
    for (int o = 128; o > 0; o >>= 1) {
        if (tid < o) red[tid] = fmaxf(red[tid], red[tid + o]);
        __syncthreads();
    }
    m = red[0];
    __syncthreads();

    float sum = 0.f;
    for (int s = tid; s < SEQ; s += 256) sum += __expf(sc[s] - m);
    red[tid] = sum;
    __syncthreads();
    for (int o = 128; o > 0; o >>= 1) {
        if (tid < o) red[tid] += red[tid + o];
        __syncthreads();
    }
    const float inv = 1.f / red[0];
    for (int s = tid; s < SEQ; s += 256)
        out[b * SEQ + s] = __expf(sc[s] - m) * inv;
}

// ---------------------------------------------------------------------------
typedef CUresult (*EncodeTiledFn)(CUtensorMap*, CUtensorMapDataType, cuuint32_t,
                                  void*, const cuuint64_t*, const cuuint64_t*,
                                  const cuuint32_t*, const cuuint32_t*,
                                  CUtensorMapInterleave, CUtensorMapSwizzle,
                                  CUtensorMapL2promotion, CUtensorMapFloatOOBfill);

static EncodeTiledFn get_encode_fn() {
    static EncodeTiledFn fn = nullptr;
    if (!fn) {
        void* h = dlopen("libcuda.so.1", RTLD_NOW | RTLD_GLOBAL);
        if (!h) h = dlopen("libcuda.so", RTLD_NOW | RTLD_GLOBAL);
        if (h) fn = (EncodeTiledFn)dlsym(h, "cuTensorMapEncodeTiled");
    }
    return fn;
}

extern "C" void kernel_launch(void* const* d_in, const int* in_sizes, int n_in,
                              void* d_out, int out_size) {
    const float* hidden = (const float*)d_in[0];
    const float* enc    = (const float*)d_in[1];
    const float* W      = (const float*)d_in[2];
    const float* bias   = (const float*)d_in[3];
    const float* v      = (const float*)d_in[4];
    float* out = (float*)d_out;

    EncodeTiledFn encode = get_encode_fn();
    void *enc_h_ptr, *wb_h_ptr;
    cudaGetSymbolAddress(&enc_h_ptr, g_enc_h);
    cudaGetSymbolAddress(&wb_h_ptr, g_wb_h);

    CUtensorMap tmap_a, tmap_b;
    {
        cuuint64_t dims[2]    = {HDIM, MROWS};
        cuuint64_t strides[1] = {HDIM * sizeof(__half)};
        cuuint32_t box[2]     = {BK, BM};
        cuuint32_t es[2]      = {1, 1};
        encode(&tmap_a, CU_TENSOR_MAP_DATA_TYPE_FLOAT16, 2, enc_h_ptr,
               dims, strides, box, es,
               CU_TENSOR_MAP_INTERLEAVE_NONE, CU_TENSOR_MAP_SWIZZLE_128B,
               CU_TENSOR_MAP_L2_PROMOTION_L2_128B, CU_TENSOR_MAP_FLOAT_OOB_FILL_NONE);
    }
    {
        cuuint64_t dims[2]    = {HDIM, HDIM};
        cuuint64_t strides[1] = {HDIM * sizeof(__half)};
        cuuint32_t box[2]     = {BK, 32};
        cuuint32_t es[2]      = {1, 1};
        encode(&tmap_b, CU_TENSOR_MAP_DATA_TYPE_FLOAT16, 2, wb_h_ptr,
               dims, strides, box, es,
               CU_TENSOR_MAP_INTERLEAVE_NONE, CU_TENSOR_MAP_SWIZZLE_128B,
               CU_TENSOR_MAP_L2_PROMOTION_L2_128B, CU_TENSOR_MAP_FLOAT_OOB_FILL_NONE);
    }

    prep_small_kernel<<<NB_W + HDIM, 256>>>(W, hidden, bias);

    cudaFuncSetAttribute(gemm_fused_kernel,
                         cudaFuncAttributeMaxDynamicSharedMemorySize, SMEM_TOTAL);
    gemm_fused_kernel<<<MROWS / BM, 288, SMEM_TOTAL>>>((const float4*)enc, tmap_a, tmap_b, v);

    softmax_kernel<<<BATCH, 256>>>(out);
}

// round 16
// speedup vs baseline: 1.0780x; 1.0780x over previous
#include <cuda_runtime.h>
#include <cuda.h>
#include <cuda_fp16.h>
#include <cstdint>
#include <math.h>
#include <dlfcn.h>

#define SEQ   2048
#define BATCH 32
#define HDIM  1024
#define MROWS (SEQ * BATCH)

#define BM    128
#define BN    128
#define NPASS 8
#define BK    64
#define KT    16
#define DEPTH 2

#define A_STAGE_BYTES (BM * 128)
#define B_STAGE_BYTES (BN * 128)
#define STAGE_BYTES   (A_STAGE_BYTES + B_STAGE_BYTES)
#define TX_BYTES      STAGE_BYTES

#define CS_OFF   (DEPTH * STAGE_BYTES)            // 65536
#define SRED_OFF (CS_OFF + 32 * 129 * 4)          // 82048
#define BAR_OFF  (SRED_OFF + 4 * 128 * 4)         // 84096
#define SMEM_TOTAL (BAR_OFF + 32 + 1024)

__device__ __align__(1024) __half g_enc_h[(size_t)MROWS * HDIM];  // 128 MB
__device__ __align__(1024) __half g_wb_h[(size_t)HDIM * HDIM];    // 2 MB
__device__ float g_c[BATCH * HDIM];
__device__ float g_scores[BATCH * SEQ];

// ---------------------------------------------------------------------------
__device__ __forceinline__ uint32_t smem_u32(const void* p) {
    uint32_t a;
    asm("{ .reg .u64 t; cvta.to.shared.u64 t, %1; cvt.u32.u64 %0, t; }" : "=r"(a) : "l"(p));
    return a;
}
__device__ __forceinline__ uint32_t elect_one() {
    uint32_t p;
    asm volatile("{ .reg .pred p; elect.sync _|p, 0xFFFFFFFF; selp.b32 %0, 1, 0, p; }" : "=r"(p));
    return p;
}

#define MBAR_INIT(a, n) \
    asm volatile("mbarrier.init.shared.b64 [%0], %1;" :: "r"(a), "r"((uint32_t)(n)) : "memory")
#define MBAR_EXPECT_TX(a, n) \
    asm volatile("mbarrier.arrive.expect_tx.shared.b64 _, [%0], %1;" :: "r"(a), "r"((uint32_t)(n)) : "memory")
#define MBAR_ARRIVE(a) \
    asm volatile("mbarrier.arrive.shared.b64 _, [%0];" :: "r"(a) : "memory")
#define MBAR_WAIT(a, ph) do { \
    uint32_t _m = (a), _p = (ph), _d; \
    asm volatile("{ .reg .pred p; mbarrier.try_wait.parity.acquire.cta.shared::cta.b64 p, [%1], %2; selp.b32 %0,1,0,p; }" \
        : "=r"(_d) : "r"(_m), "r"(_p) : "memory"); \
    if (!_d) { \
        asm volatile("{ .reg .pred P1;\nWL_%=:\n mbarrier.try_wait.parity.acquire.cta.shared::cta.b64 P1, [%0], %1, 0x989680;\n @P1 bra.uni WD_%=;\n bra.uni WL_%=;\nWD_%=:\n}" \
            :: "r"(_m), "r"(_p) : "memory"); \
    } } while (0)

#define TMA2D_CTA(smem, map, x, y, bar) \
    asm volatile("cp.async.bulk.tensor.2d.shared::cta.global.tile.mbarrier::complete_tx::bytes [%0], [%1, {%2, %3}], [%4];" \
        :: "r"(smem), "l"(map), "r"((int)(x)), "r"((int)(y)), "r"(bar) : "memory")

#define LDSM4(r, a) \
    asm volatile("ldmatrix.sync.aligned.m8n8.x4.shared.b16 {%0,%1,%2,%3}, [%4];" \
        : "=r"((r)[0]), "=r"((r)[1]), "=r"((r)[2]), "=r"((r)[3]) : "r"(a))

__device__ __forceinline__ void mma_f16(float* c, const uint32_t* a, uint32_t b0, uint32_t b1) {
    asm volatile(
        "mma.sync.aligned.m16n8k16.row.col.f32.f16.f16.f32 "
        "{%0,%1,%2,%3}, {%4,%5,%6,%7}, {%8,%9}, {%0,%1,%2,%3};"
        : "+f"(c[0]), "+f"(c[1]), "+f"(c[2]), "+f"(c[3])
        : "r"(a[0]), "r"(a[1]), "r"(a[2]), "r"(a[3]), "r"(b0), "r"(b1));
}

__device__ __forceinline__ float fast_tanh(float x) {
    float e, r;
    asm("ex2.approx.f32 %0, %1;" : "=f"(e) : "f"(x * 2.8853900817779268f));
    asm("rcp.approx.f32 %0, %1;" : "=f"(r) : "f"(e + 1.0f));
    return fmaf(-2.0f, r, 1.0f);
}
__device__ __forceinline__ uint32_t pack2h(float a, float b) {
    __half2 h = __floats2half2_rn(a, b);
    return *(uint32_t*)&h;
}
__device__ __forceinline__ float4 ldcs4(const float4* p) {
    float4 r;
    asm("ld.global.cs.v4.f32 {%0,%1,%2,%3}, [%4];"
        : "=f"(r.x), "=f"(r.y), "=f"(r.z), "=f"(r.w) : "l"(p));
    return r;
}

// ---------------------------------------------------------------------------
// Fused prep: blocks [0, NB_ENC) convert enc; [NB_ENC, +NB_W) convert W;
// [NB_ENC+NB_W, +1024) compute c.
// ---------------------------------------------------------------------------
#define NB_ENC (MROWS * HDIM / 16 / 256)  // 16384
#define NB_W   (HDIM * HDIM / 8 / 256)    // 512

__global__ __launch_bounds__(256)
void prep_all_kernel(const float4* __restrict__ enc4,
                     const float* __restrict__ W,
                     const float* __restrict__ hidden,
                     const float* __restrict__ bias) {
    const int bx = blockIdx.x;
    if (bx < NB_ENC) {
        size_t i0 = (size_t)bx * 512 + threadIdx.x;
        #pragma unroll
        for (int c = 0; c < 2; c++) {
            size_t i = i0 + (size_t)c * 256;
            float4 f0 = ldcs4(&enc4[2 * i]);
            float4 f1 = ldcs4(&enc4[2 * i + 1]);
            uint4 o;
            o.x = pack2h(f0.x, f0.y); o.y = pack2h(f0.z, f0.w);
            o.z = pack2h(f1.x, f1.y); o.w = pack2h(f1.z, f1.w);
            ((uint4*)g_enc_h)[i] = o;
        }
        return;
    }
    if (bx < NB_ENC + NB_W) {
        size_t i = (size_t)(bx - NB_ENC) * 256 + threadIdx.x;
        int n = (int)(i >> 7), k8 = ((int)i & 127) * 8;
        const float4* src = (const float4*)(W + (size_t)n * (2 * HDIM) + HDIM + k8);
        float4 f0 = src[0], f1 = src[1];
        uint4 o;
        o.x = pack2h(f0.x, f0.y); o.y = pack2h(f0.z, f0.w);
        o.z = pack2h(f1.x, f1.y); o.w = pack2h(f1.z, f1.w);
        ((uint4*)g_wb_h)[i] = o;
        return;
    }
    // prep_c: one block per k
    __shared__ float sw[HDIM];
    const int k = bx - NB_ENC - NB_W;
    const int tid = threadIdx.x;
    for (int j = tid; j < HDIM; j += 256) sw[j] = W[(size_t)k * (2 * HDIM) + j];
    __syncthreads();
    const int w = tid >> 5, l = tid & 31;
    const float bk = bias[k];
    for (int b = w; b < 32; b += 8) {
        const float* h = hidden + (size_t)b * HDIM;
        float acc = 0.f;
        #pragma unroll 8
        for (int j = l; j < HDIM; j += 32) acc += h[j] * sw[j];
        acc += __shfl_xor_sync(~0u, acc, 16);
        acc += __shfl_xor_sync(~0u, acc, 8);
        acc += __shfl_xor_sync(~0u, acc, 4);
        acc += __shfl_xor_sync(~0u, acc, 2);
        acc += __shfl_xor_sync(~0u, acc, 1);
        if (l == 0) g_c[b * HDIM + k] = acc + bk;
    }
}

// ---------------------------------------------------------------------------
// Fused GEMM: r10 pipeline WITHOUT the cluster. Per-CTA unicast TMA for both
// A and B, DEPTH=2, cs in smem, local empty barriers. 2 CTAs/SM.
// ---------------------------------------------------------------------------
__global__ __launch_bounds__(288, 2)
void gemm_fused_kernel(const __grid_constant__ CUtensorMap tmap_a,
                       const __grid_constant__ CUtensorMap tmap_b,
                       const float* __restrict__ v) {
    extern __shared__ char smem_raw[];
    const uint32_t sraw = smem_u32(smem_raw);
    const uint32_t base = (sraw + 1023u) & ~1023u;
    char* sm = smem_raw + (base - sraw);

    const int tid  = threadIdx.x;
    const int wid  = tid >> 5;
    const int lane = tid & 31;
    const int m0 = blockIdx.x * BM;

    float* cs   = (float*)(sm + CS_OFF);    // [32][129]
    float* sred = (float*)(sm + SRED_OFF);  // [4][128]

    const uint32_t full0  = base + BAR_OFF;        // DEPTH x 8
    const uint32_t empty0 = base + BAR_OFF + 16;   // DEPTH x 8

    if (tid == 0) {
        #pragma unroll
        for (int s = 0; s < DEPTH; s++) {
            MBAR_INIT(full0  + s * 8, 1);
            MBAR_INIT(empty0 + s * 8, 8);   // 8 local consumer warps
        }
    }
    __syncthreads();

    if (wid == 8) {
        // -------- TMA producer --------
        if (elect_one()) {
            int stage = 0, ph = 1;
            for (int i = 0; i < NPASS * KT; i++) {
                const int p = i >> 4, kt = i & 15;
                MBAR_WAIT(empty0 + stage * 8, ph);
                const uint32_t fb = full0 + stage * 8;
                MBAR_EXPECT_TX(fb, TX_BYTES);
                const uint32_t a_dst = base + stage * STAGE_BYTES;
                const uint32_t b_dst = a_dst + A_STAGE_BYTES;
                TMA2D_CTA(a_dst, &tmap_a, kt * BK, m0, fb);
                TMA2D_CTA(b_dst, &tmap_b, kt * BK, p * BN, fb);
                if (++stage == DEPTH) { stage = 0; ph ^= 1; }
            }
        }
    } else {
        // -------- consumers: warps 0-7, warp tile 64x32 --------
        const int warp_m = wid >> 2;
        const int warp_n = wid & 3;

        float acc[4][4][4];
        float score[8];
        #pragma unroll
        for (int i = 0; i < 8; i++) score[i] = 0.f;
        #pragma unroll
        for (int mt = 0; mt < 4; mt++)
            #pragma unroll
            for (int nt = 0; nt < 4; nt++)
                #pragma unroll
                for (int i = 0; i < 4; i++) acc[mt][nt][i] = 0.f;

        const int g   = lane >> 2;
        const int tig = lane & 3;
        const int a_row = warp_m * 64 + (lane & 15);
        const uint32_t a_ghi = (uint32_t)(lane >> 4);
        const int b_row = warp_n * 32 + ((lane >> 3) & 1) * 8 + (lane & 7);

        int stage = 0, fph = 0;
        for (int p = 0; p < NPASS; p++) {
            asm volatile("bar.sync 1, 256;" ::: "memory");
            for (int idx = tid; idx < 32 * BN; idx += 256) {
                const int b = idx >> 7, nn = idx & 127;
                cs[b * 129 + nn] = g_c[b * HDIM + p * BN + nn];
            }
            asm volatile("bar.sync 1, 256;" ::: "memory");

            for (int kt = 0; kt < KT; kt++) {
                MBAR_WAIT(full0 + stage * 8, fph);
                const uint32_t a_base = base + stage * STAGE_BYTES;
                const uint32_t b_base = a_base + A_STAGE_BYTES;
                #pragma unroll
                for (int ks = 0; ks < 4; ks++) {
                    const uint32_t gr = (uint32_t)(ks * 2) + a_ghi;
                    uint32_t aF[4][4], bF[2][4];
                    #pragma unroll
                    for (int mt = 0; mt < 4; mt++) {
                        const int r = a_row + mt * 16;
                        LDSM4(aF[mt], a_base + r * 128 + ((gr ^ (uint32_t)(r & 7)) << 4));
                    }
                    #pragma unroll
                    for (int ntp = 0; ntp < 2; ntp++) {
                        const int n = b_row + ntp * 16;
                        LDSM4(bF[ntp], b_base + n * 128 + ((gr ^ (uint32_t)(n & 7)) << 4));
                    }
                    #pragma unroll
                    for (int mt = 0; mt < 4; mt++)
                        #pragma unroll
                        for (int ntp = 0; ntp < 2; ntp++) {
                            mma_f16(acc[mt][2 * ntp],     aF[mt], bF[ntp][0], bF[ntp][2]);
                            mma_f16(acc[mt][2 * ntp + 1], aF[mt], bF[ntp][1], bF[ntp][3]);
                        }
                }
                if (lane == 0) MBAR_ARRIVE(empty0 + stage * 8);
                if (++stage == DEPTH) { stage = 0; fph ^= 1; }
            }

            // epilogue: tanh + v-dot
            #pragma unroll
            for (int mt = 0; mt < 4; mt++) {
                #pragma unroll
                for (int nt = 0; nt < 4; nt++) {
                    #pragma unroll
                    for (int i = 0; i < 4; i++) {
                        const int rl  = mt * 16 + g + ((i >> 1) << 3);
                        const int b   = rl & 31;
                        const int col = warp_n * 32 + nt * 8 + (tig << 1) + (i & 1);
                        const float vv = __ldg(&v[p * BN + col]);
                        score[mt * 2 + (i >> 1)] +=
                            fast_tanh(acc[mt][nt][i] + cs[b * 129 + col]) * vv;
                        acc[mt][nt][i] = 0.f;
                    }
                }
            }
        }

        #pragma unroll
        for (int slot = 0; slot < 8; slot++) {
            float sv = score[slot];
            sv += __shfl_xor_sync(0xFFFFFFFFu, sv, 1);
            sv += __shfl_xor_sync(0xFFFFFFFFu, sv, 2);
            if (tig == 0) {
                const int rl = warp_m * 64 + (slot >> 1) * 16 + g + ((slot & 1) << 3);
                sred[warp_n * 128 + rl] = sv;
            }
        }
        asm volatile("bar.sync 1, 256;" ::: "memory");
        if (tid < BM) {
            const float t = sred[tid] + sred[128 + tid] + sred[256 + tid] + sred[384 + tid];
            const int m = m0 + tid;
            g_scores[(m & 31) * SEQ + (m >> 5)] = t;
        }
    }
}

// ---------------------------------------------------------------------------
__global__ void softmax_kernel(float* __restrict__ out) {
    __shared__ float red[256];
    const int b = blockIdx.x, tid = threadIdx.x;
    const float* sc = g_scores + b * SEQ;

    float m = -1e30f;
    for (int s = tid; s < SEQ; s += 256) m = fmaxf(m, sc[s]);
    red[tid] = m;
    __syncthreads();
    for (int o = 128; o > 0; o >>= 1) {
        if (tid < o) red[tid] = fmaxf(red[tid], red[tid + o]);
        __syncthreads();
    }
    m = red[0];
    __syncthreads();

    float sum = 0.f;
    for (int s = tid; s < SEQ; s += 256) sum += __expf(sc[s] - m);
    red[tid] = sum;
    __syncthreads();
    for (int o = 128; o > 0; o >>= 1) {
        if (tid < o) red[tid] += red[tid + o];
        __syncthreads();
    }
    const float inv = 1.f / red[0];
    for (int s = tid; s < SEQ; s += 256)
        out[b * SEQ + s] = __expf(sc[s] - m) * inv;
}

// ---------------------------------------------------------------------------
typedef CUresult (*EncodeTiledFn)(CUtensorMap*, CUtensorMapDataType, cuuint32_t,
                                  void*, const cuuint64_t*, const cuuint64_t*,
                                  const cuuint32_t*, const cuuint32_t*,
                                  CUtensorMapInterleave, CUtensorMapSwizzle,
                                  CUtensorMapL2promotion, CUtensorMapFloatOOBfill);

static EncodeTiledFn get_encode_fn() {
    static EncodeTiledFn fn = nullptr;
    if (!fn) {
        void* h = dlopen("libcuda.so.1", RTLD_NOW | RTLD_GLOBAL);
        if (!h) h = dlopen("libcuda.so", RTLD_NOW | RTLD_GLOBAL);
        if (h) fn = (EncodeTiledFn)dlsym(h, "cuTensorMapEncodeTiled");
    }
    return fn;
}

extern "C" void kernel_launch(void* const* d_in, const int* in_sizes, int n_in,
                              void* d_out, int out_size) {
    const float* hidden = (const float*)d_in[0];
    const float* enc    = (const float*)d_in[1];
    const float* W      = (const float*)d_in[2];
    const float* bias   = (const float*)d_in[3];
    const float* v      = (const float*)d_in[4];
    float* out = (float*)d_out;

    EncodeTiledFn encode = get_encode_fn();
    void *enc_h_ptr, *wb_h_ptr;
    cudaGetSymbolAddress(&enc_h_ptr, g_enc_h);
    cudaGetSymbolAddress(&wb_h_ptr, g_wb_h);

    CUtensorMap tmap_a, tmap_b;
    {
        cuuint64_t dims[2]    = {HDIM, MROWS};
        cuuint64_t strides[1] = {HDIM * sizeof(__half)};
        cuuint32_t box[2]     = {BK, BM};
        cuuint32_t es[2]      = {1, 1};
        encode(&tmap_a, CU_TENSOR_MAP_DATA_TYPE_FLOAT16, 2, enc_h_ptr,
               dims, strides, box, es,
               CU_TENSOR_MAP_INTERLEAVE_NONE, CU_TENSOR_MAP_SWIZZLE_128B,
               CU_TENSOR_MAP_L2_PROMOTION_L2_128B, CU_TENSOR_MAP_FLOAT_OOB_FILL_NONE);
    }
    {
        cuuint64_t dims[2]    = {HDIM, HDIM};
        cuuint64_t strides[1] = {HDIM * sizeof(__half)};
        cuuint32_t box[2]     = {BK, BN};
        cuuint32_t es[2]      = {1, 1};
        encode(&tmap_b, CU_TENSOR_MAP_DATA_TYPE_FLOAT16, 2, wb_h_ptr,
               dims, strides, box, es,
               CU_TENSOR_MAP_INTERLEAVE_NONE, CU_TENSOR_MAP_SWIZZLE_128B,
               CU_TENSOR_MAP_L2_PROMOTION_L2_128B, CU_TENSOR_MAP_FLOAT_OOB_FILL_NONE);
    }

    prep_all_kernel<<<NB_ENC + NB_W + HDIM, 256>>>((const float4*)enc, W, hidden, bias);

    cudaFuncSetAttribute(gemm_fused_kernel,
                         cudaFuncAttributeMaxDynamicSharedMemorySize, SMEM_TOTAL);
    gemm_fused_kernel<<<MROWS / BM, 288, SMEM_TOTAL>>>(tmap_a, tmap_b, v);

    softmax_kernel<<<BATCH, 256>>>(out);
}